// round 1
// baseline (speedup 1.0000x reference)
#include <cuda_runtime.h>
#include <math.h>

#define BATCH  16
#define CDIM   256
#define NPIX   4096
#define NHEADS 4
#define DHEAD  32
#define HID    128
#define QKVM   384

// Scratch (device globals: allocation-free per harness rules)
__device__ float g_qkv[BATCH * QKVM * NPIX];                  // 96 MB (k_proj rows left untouched)
__device__ float g_k  [BATCH * HID  * NPIX];                  // 32 MB
__device__ float g_ctx[BATCH * NHEADS * DHEAD * DHEAD];       // 256 KB
__device__ float g_W2 [BATCH * CDIM * HID];                   // 2 MB

// ---------------------------------------------------------------------------
// Generic 64x64 tile GEMM, C[b] = A[b] (MxK row-major) * B[b] (Kx4096 row-major)
// 256 threads, 4x4 micro-tile per thread, BK=16.
// remap=1: grid.y=4 maps block rows {0,1,4,5} of a 384-row output (skip k_proj).
// ---------------------------------------------------------------------------
__global__ void gemm64(const float* __restrict__ A, const float* __restrict__ B,
                       float* __restrict__ C, int K,
                       size_t sA, size_t sB, size_t sC, int remap)
{
    int b  = blockIdx.z;
    int bm = blockIdx.y;
    if (remap && bm >= 2) bm += 2;

    const float* Ab = A + (size_t)b * sA;
    const float* Bb = B + (size_t)b * sB;
    float*       Cb = C + (size_t)b * sC;

    int row0 = bm * 64;
    int col0 = blockIdx.x * 64;
    int tid  = threadIdx.x;
    int tx   = tid & 15, ty = tid >> 4;

    __shared__ float As[16][64];
    __shared__ float Bs[16][64];

    float acc[4][4] = {};

    for (int k0 = 0; k0 < K; k0 += 16) {
        // A tile 64x16 (transposed into [k][m])
        {
            int r  = tid >> 2;            // 0..63
            int kc = (tid & 3) * 4;
            float4 a = *(const float4*)&Ab[(size_t)(row0 + r) * K + k0 + kc];
            As[kc + 0][r] = a.x;
            As[kc + 1][r] = a.y;
            As[kc + 2][r] = a.z;
            As[kc + 3][r] = a.w;
        }
        // B tile 16x64
        {
            int r = tid >> 4;             // 0..15
            int c = (tid & 15) * 4;
            *(float4*)&Bs[r][c] =
                *(const float4*)&Bb[(size_t)(k0 + r) * NPIX + col0 + c];
        }
        __syncthreads();
#pragma unroll
        for (int kk = 0; kk < 16; kk++) {
            float4 a4 = *(float4*)&As[kk][ty * 4];
            float4 b4 = *(float4*)&Bs[kk][tx * 4];
            float av[4] = {a4.x, a4.y, a4.z, a4.w};
            float bv[4] = {b4.x, b4.y, b4.z, b4.w};
#pragma unroll
            for (int i = 0; i < 4; i++)
#pragma unroll
                for (int j = 0; j < 4; j++)
                    acc[i][j] = fmaf(av[i], bv[j], acc[i][j]);
        }
        __syncthreads();
    }
#pragma unroll
    for (int i = 0; i < 4; i++) {
        float4 o = {acc[i][0], acc[i][1], acc[i][2], acc[i][3]};
        *(float4*)&Cb[(size_t)(row0 + ty * 4 + i) * NPIX + col0 + tx * 4] = o;
    }
}

// ---------------------------------------------------------------------------
// Softmax over n (axis=-1), in place on the q region of g_qkv.
// One block per row (16*128 rows), 256 threads, 16 elems/thread in registers.
// ---------------------------------------------------------------------------
__global__ void softmax_n_kernel()
{
    int r = blockIdx.x;                // 0..2047
    int b = r >> 7, q = r & 127;
    float* row = g_qkv + (size_t)b * QKVM * NPIX + (size_t)q * NPIX;
    int tid = threadIdx.x;

    float v[16];
    float m = -1e30f;
#pragma unroll
    for (int i = 0; i < 16; i++) { v[i] = row[tid + i * 256]; m = fmaxf(m, v[i]); }

    __shared__ float red[8];
#pragma unroll
    for (int o = 16; o > 0; o >>= 1) m = fmaxf(m, __shfl_xor_sync(~0u, m, o));
    if ((tid & 31) == 0) red[tid >> 5] = m;
    __syncthreads();
    m = red[0];
#pragma unroll
    for (int i = 1; i < 8; i++) m = fmaxf(m, red[i]);
    __syncthreads();

    float s = 0.f;
#pragma unroll
    for (int i = 0; i < 16; i++) { v[i] = __expf(v[i] - m); s += v[i]; }
#pragma unroll
    for (int o = 16; o > 0; o >>= 1) s += __shfl_xor_sync(~0u, s, o);
    if ((tid & 31) == 0) red[tid >> 5] = s;
    __syncthreads();
    s = red[0];
#pragma unroll
    for (int i = 1; i < 8; i++) s += red[i];
    float inv = 1.0f / s;
#pragma unroll
    for (int i = 0; i < 16; i++) row[tid + i * 256] = v[i] * inv;
}

// ---------------------------------------------------------------------------
// Softmax over d (axis=-2): one thread per (b,h,n) column of 32 strided values.
// Reads softmaxed q from g_qkv, writes g_k. Coalesced across n.
// ---------------------------------------------------------------------------
__global__ void softmax_d_kernel()
{
    int idx = blockIdx.x * 256 + threadIdx.x;     // 0 .. 262143
    int b   = idx >> 14;
    int rem = idx & 16383;
    int h   = rem >> 12;
    int n   = rem & 4095;

    const float* qp = g_qkv + (size_t)b * QKVM * NPIX + (size_t)(h * DHEAD) * NPIX + n;
    float e[32];
    float m = -1e30f;
#pragma unroll
    for (int d = 0; d < 32; d++) { e[d] = qp[(size_t)d * NPIX]; m = fmaxf(m, e[d]); }
    float s = 0.f;
#pragma unroll
    for (int d = 0; d < 32; d++) { e[d] = __expf(e[d] - m); s += e[d]; }
    float inv = 1.0f / s;

    float* kp = g_k + (size_t)b * HID * NPIX + (size_t)(h * DHEAD) * NPIX + n;
#pragma unroll
    for (int d = 0; d < 32; d++) kp[(size_t)d * NPIX] = e[d] * inv;
}

// ---------------------------------------------------------------------------
// context[b,h,k,v] = sum_n k[b,h,k,n] * v[b,h,v,n].  One block per (b,h).
// ---------------------------------------------------------------------------
__global__ void ctx_kernel()
{
    int b = blockIdx.x >> 2, h = blockIdx.x & 3;
    const float* kp = g_k   + ((size_t)b * HID  + h * DHEAD) * NPIX;
    const float* vp = g_qkv + ((size_t)b * QKVM + 2 * HID + h * DHEAD) * NPIX;

    __shared__ float ks[32][128];
    __shared__ float vs[32][128];

    int tid = threadIdx.x;
    int tx = tid & 15, ty = tid >> 4;
    float acc[2][2] = {};

    for (int n0 = 0; n0 < NPIX; n0 += 128) {
#pragma unroll
        for (int r = 0; r < 4; r++) {
            int li  = tid + r * 256;
            int row = li >> 5;
            int col = (li & 31) * 4;
            *(float4*)&ks[row][col] = *(const float4*)&kp[(size_t)row * NPIX + n0 + col];
            *(float4*)&vs[row][col] = *(const float4*)&vp[(size_t)row * NPIX + n0 + col];
        }
        __syncthreads();
#pragma unroll 4
        for (int j = 0; j < 128; j++) {
            float k0v = ks[ty * 2][j],     k1v = ks[ty * 2 + 1][j];
            float v0v = vs[tx * 2][j],     v1v = vs[tx * 2 + 1][j];
            acc[0][0] = fmaf(k0v, v0v, acc[0][0]);
            acc[0][1] = fmaf(k0v, v1v, acc[0][1]);
            acc[1][0] = fmaf(k1v, v0v, acc[1][0]);
            acc[1][1] = fmaf(k1v, v1v, acc[1][1]);
        }
        __syncthreads();
    }
    float* cp = g_ctx + (size_t)blockIdx.x * DHEAD * DHEAD;
#pragma unroll
    for (int i = 0; i < 2; i++)
#pragma unroll
        for (int j = 0; j < 2; j++)
            cp[(ty * 2 + i) * DHEAD + tx * 2 + j] = acc[i][j];
}

// ---------------------------------------------------------------------------
// W2[b,o,h*32+k] = sum_v w_out[o, h*32+v] * ctx[b,h,k,v]
// (composes output projection with the context matmul: kills one big GEMM)
// ---------------------------------------------------------------------------
__global__ void w2_kernel(const float* __restrict__ w_out)
{
    int idx = blockIdx.x * 256 + threadIdx.x;   // 16*256*128 = 524288
    int b   = idx >> 15;
    int rem = idx & 32767;
    int o   = rem >> 7;
    int c2  = rem & 127;
    int h   = c2 >> 5, kk = c2 & 31;

    const float* wrow = w_out + o * HID + h * DHEAD;
    const float* cp   = g_ctx + (((size_t)b * NHEADS + h) * DHEAD + kk) * DHEAD;
    float s = 0.f;
#pragma unroll
    for (int v = 0; v < 32; v++) s = fmaf(wrow[v], cp[v], s);
    g_W2[idx] = s;
}

// ---------------------------------------------------------------------------
extern "C" void kernel_launch(void* const* d_in, const int* in_sizes, int n_in,
                              void* d_out, int out_size)
{
    const float* x     = (const float*)d_in[0];
    const float* w_qkv = (const float*)d_in[1];
    const float* w_out = (const float*)d_in[2];
    float*       out   = (float*)d_out;

    float *qkv_p, *w2_p;
    cudaGetSymbolAddress((void**)&qkv_p, g_qkv);
    cudaGetSymbolAddress((void**)&w2_p,  g_W2);

    dim3 gg(NPIX / 64, 4, BATCH);

    // 1) q and v projections (skip unused k_proj rows via remap)
    gemm64<<<gg, 256>>>(w_qkv, x, qkv_p, CDIM,
                        0, (size_t)CDIM * NPIX, (size_t)QKVM * NPIX, 1);
    // 2) softmax over n (in place on q)
    softmax_n_kernel<<<BATCH * HID, 256>>>();
    // 3) softmax over d -> k
    softmax_d_kernel<<<(BATCH * NHEADS * NPIX) / 256, 256>>>();
    // 4) context = k @ v^T
    ctx_kernel<<<BATCH * NHEADS, 256>>>();
    // 5) compose W2 = w_out ∘ context
    w2_kernel<<<(BATCH * CDIM * HID) / 256, 256>>>(w_out);
    // 6) y = W2 @ q  (fused attention-out + output projection)
    gemm64<<<gg, 256>>>(w2_p, qkv_p, out, HID,
                        (size_t)CDIM * HID, (size_t)QKVM * NPIX, (size_t)CDIM * NPIX, 0);
}

// round 2
// speedup vs baseline: 1.6410x; 1.6410x over previous
#include <cuda_runtime.h>
#include <math.h>

#define BATCH  16
#define CDIM   256
#define NPIX   4096
#define NHEADS 4
#define DHEAD  32
#define HID    128
#define NCHUNK 32
#define CHW    128            // chunk width in n

// Scratch (device globals: allocation-free per harness rules)
__device__ float g_qkv [BATCH * 256 * NPIX];                 // rows 0-127 = q, 128-255 = v (64 MB)
__device__ float g_ctxp[NCHUNK * BATCH * NHEADS * DHEAD * DHEAD]; // 8 MB partials
__device__ float g_ctx [BATCH * NHEADS * DHEAD * DHEAD];
__device__ float g_W2  [BATCH * CDIM * HID];

// ---------------------------------------------------------------------------
// 128x128-tile GEMM, 8x8 micro-tile, BK=16, 256 threads.
// C[b](rows bm*128..) = A[b](rows bm*aJump.., MxK row-major) * B[b](K x 4096)
// ---------------------------------------------------------------------------
__global__ void gemm128(const float* __restrict__ A, const float* __restrict__ B,
                        float* __restrict__ C, int K,
                        size_t sA, size_t sB, size_t sC, int aJump)
{
    int b  = blockIdx.z;
    const float* Ab = A + (size_t)b * sA + (size_t)(blockIdx.y * aJump) * K;
    const float* Bb = B + (size_t)b * sB + blockIdx.x * 128;
    float*       Cb = C + (size_t)b * sC + (size_t)(blockIdx.y * 128) * NPIX + blockIdx.x * 128;

    __shared__ float As[16][128];   // [k][m]
    __shared__ float Bs[16][128];   // [k][n]

    int tid = threadIdx.x;
    int tx  = tid & 15;             // n-group (8 cols)
    int ty  = tid >> 4;             // m-group (8 rows)

    int ar  = tid & 127;            // A loader: row
    int akc = (tid >> 7) * 8;       // A loader: k base (0 or 8)
    int br  = tid >> 4;             // B loader: row 0..15
    int bc  = (tid & 15) * 8;       // B loader: col base

    float acc[8][8] = {};

    for (int k0 = 0; k0 < K; k0 += 16) {
#pragma unroll
        for (int u = 0; u < 2; u++) {
            float4 a = *(const float4*)&Ab[(size_t)ar * K + k0 + akc + u * 4];
            As[akc + u * 4 + 0][ar] = a.x;
            As[akc + u * 4 + 1][ar] = a.y;
            As[akc + u * 4 + 2][ar] = a.z;
            As[akc + u * 4 + 3][ar] = a.w;
        }
#pragma unroll
        for (int u = 0; u < 2; u++)
            *(float4*)&Bs[br][bc + u * 4] =
                *(const float4*)&Bb[(size_t)(k0 + br) * NPIX + bc + u * 4];
        __syncthreads();
#pragma unroll
        for (int kk = 0; kk < 16; kk++) {
            float av[8], bv[8];
            *(float4*)&av[0] = *(float4*)&As[kk][ty * 8];
            *(float4*)&av[4] = *(float4*)&As[kk][ty * 8 + 4];
            *(float4*)&bv[0] = *(float4*)&Bs[kk][tx * 8];
            *(float4*)&bv[4] = *(float4*)&Bs[kk][tx * 8 + 4];
#pragma unroll
            for (int i = 0; i < 8; i++)
#pragma unroll
                for (int j = 0; j < 8; j++)
                    acc[i][j] = fmaf(av[i], bv[j], acc[i][j]);
        }
        __syncthreads();
    }
#pragma unroll
    for (int i = 0; i < 8; i++) {
        float* crow = &Cb[(size_t)(ty * 8 + i) * NPIX + tx * 8];
        float4 o0 = {acc[i][0], acc[i][1], acc[i][2], acc[i][3]};
        float4 o1 = {acc[i][4], acc[i][5], acc[i][6], acc[i][7]};
        *(float4*)&crow[0] = o0;
        *(float4*)&crow[4] = o1;
    }
}

// ---------------------------------------------------------------------------
// Softmax over n (axis=-1), in place on q rows of g_qkv.
// ---------------------------------------------------------------------------
__global__ void softmax_n_kernel()
{
    int r = blockIdx.x;                 // 0..2047
    int b = r >> 7, q = r & 127;
    float* row = g_qkv + (size_t)b * 256 * NPIX + (size_t)q * NPIX;
    int tid = threadIdx.x;

    float v[16];
    float m = -1e30f;
#pragma unroll
    for (int i = 0; i < 16; i++) { v[i] = row[tid + i * 256]; m = fmaxf(m, v[i]); }

    __shared__ float red[8];
#pragma unroll
    for (int o = 16; o > 0; o >>= 1) m = fmaxf(m, __shfl_xor_sync(~0u, m, o));
    if ((tid & 31) == 0) red[tid >> 5] = m;
    __syncthreads();
    m = red[0];
#pragma unroll
    for (int i = 1; i < 8; i++) m = fmaxf(m, red[i]);
    __syncthreads();

    float s = 0.f;
#pragma unroll
    for (int i = 0; i < 16; i++) { v[i] = __expf(v[i] - m); s += v[i]; }
#pragma unroll
    for (int o = 16; o > 0; o >>= 1) s += __shfl_xor_sync(~0u, s, o);
    if ((tid & 31) == 0) red[tid >> 5] = s;
    __syncthreads();
    s = red[0];
#pragma unroll
    for (int i = 1; i < 8; i++) s += red[i];
    float inv = 1.0f / s;
#pragma unroll
    for (int i = 0; i < 16; i++) row[tid + i * 256] = v[i] * inv;
}

// ---------------------------------------------------------------------------
// Fused: per-column softmax over d (axis=-2) + partial context GEMM.
// One block per (b, h, n-chunk of 128). Tiles stored n-major ([n][d], pad 33)
// so all smem accesses are conflict-free in the FMA loop.
// partial[ch][b,h][k,v] = sum_{n in chunk} softmax_d(q)[k,n] * v[v,n]
// ---------------------------------------------------------------------------
__global__ void ctx_part_kernel()
{
    int bid = blockIdx.x;               // 0..2047
    int ch  = bid & 31;
    int bh  = bid >> 5;                 // 0..63
    int b   = bh >> 2, h = bh & 3;
    int n0  = ch * CHW;

    const float* qp = g_qkv + ((size_t)b * 256 + h * DHEAD) * NPIX + n0;
    const float* vp = g_qkv + ((size_t)b * 256 + 128 + h * DHEAD) * NPIX + n0;

    __shared__ float kst[CHW][DHEAD + 1];   // [n][d] (q, becomes k after softmax)
    __shared__ float vst[CHW][DHEAD + 1];   // [n][d]

    int tid = threadIdx.x;

    // load + transpose: 1024 float4 per tile, 4 per thread
#pragma unroll
    for (int r = 0; r < 4; r++) {
        int idx = tid + r * 256;
        int row = idx >> 5;             // d 0..31
        int col = (idx & 31) * 4;       // n within chunk
        float4 qv = *(const float4*)&qp[(size_t)row * NPIX + col];
        kst[col + 0][row] = qv.x; kst[col + 1][row] = qv.y;
        kst[col + 2][row] = qv.z; kst[col + 3][row] = qv.w;
        float4 vv = *(const float4*)&vp[(size_t)row * NPIX + col];
        vst[col + 0][row] = vv.x; vst[col + 1][row] = vv.y;
        vst[col + 2][row] = vv.z; vst[col + 3][row] = vv.w;
    }
    __syncthreads();

    // per-column softmax over d (128 columns, threads 0..127)
    if (tid < CHW) {
        float e[DHEAD];
        float m = -1e30f;
#pragma unroll
        for (int d = 0; d < DHEAD; d++) { e[d] = kst[tid][d]; m = fmaxf(m, e[d]); }
        float s = 0.f;
#pragma unroll
        for (int d = 0; d < DHEAD; d++) { e[d] = __expf(e[d] - m); s += e[d]; }
        float inv = 1.0f / s;
#pragma unroll
        for (int d = 0; d < DHEAD; d++) kst[tid][d] = e[d] * inv;
    }
    __syncthreads();

    // partial ctx: 2x2 micro-tile per thread over (k, v)
    int tx = tid & 15, ty = tid >> 4;
    float acc[2][2] = {};
#pragma unroll 4
    for (int j = 0; j < CHW; j++) {
        float k0 = kst[j][ty * 2],     k1 = kst[j][ty * 2 + 1];
        float v0 = vst[j][tx * 2],     v1 = vst[j][tx * 2 + 1];
        acc[0][0] = fmaf(k0, v0, acc[0][0]);
        acc[0][1] = fmaf(k0, v1, acc[0][1]);
        acc[1][0] = fmaf(k1, v0, acc[1][0]);
        acc[1][1] = fmaf(k1, v1, acc[1][1]);
    }
    float* pp = g_ctxp + (size_t)ch * (64 * 1024) + (size_t)bh * 1024;
#pragma unroll
    for (int i = 0; i < 2; i++)
#pragma unroll
        for (int j = 0; j < 2; j++)
            pp[(ty * 2 + i) * DHEAD + tx * 2 + j] = acc[i][j];
}

__global__ void ctx_reduce_kernel()
{
    int idx = blockIdx.x * 256 + threadIdx.x;   // 0..65535
    float s = 0.f;
#pragma unroll
    for (int ch = 0; ch < NCHUNK; ch++) s += g_ctxp[(size_t)ch * 65536 + idx];
    g_ctx[idx] = s;
}

// ---------------------------------------------------------------------------
// W2[b,o,h*32+k] = sum_v w_out[o, h*32+v] * ctx[b,h,k,v]
// ---------------------------------------------------------------------------
__global__ void w2_kernel(const float* __restrict__ w_out)
{
    int idx = blockIdx.x * 256 + threadIdx.x;
    int b   = idx >> 15;
    int rem = idx & 32767;
    int o   = rem >> 7;
    int c2  = rem & 127;
    int h   = c2 >> 5, kk = c2 & 31;

    const float* wrow = w_out + o * HID + h * DHEAD;
    const float* cp   = g_ctx + (((size_t)b * NHEADS + h) * DHEAD + kk) * DHEAD;
    float s = 0.f;
#pragma unroll
    for (int v = 0; v < 32; v++) s = fmaf(wrow[v], cp[v], s);
    g_W2[idx] = s;
}

// ---------------------------------------------------------------------------
extern "C" void kernel_launch(void* const* d_in, const int* in_sizes, int n_in,
                              void* d_out, int out_size)
{
    const float* x     = (const float*)d_in[0];
    const float* w_qkv = (const float*)d_in[1];
    const float* w_out = (const float*)d_in[2];
    float*       out   = (float*)d_out;

    float *qkv_p, *w2_p;
    cudaGetSymbolAddress((void**)&qkv_p, g_qkv);
    cudaGetSymbolAddress((void**)&w2_p,  g_W2);

    dim3 gg(NPIX / 128, 2, BATCH);   // 32 x 2 x 16 = 1024 blocks

    // 1) q and v projections: A rows {0-127, 256-383} of w_qkv -> C rows {0-127,128-255}
    gemm128<<<gg, 256>>>(w_qkv, x, qkv_p, CDIM,
                         0, (size_t)CDIM * NPIX, (size_t)256 * NPIX, 256);
    // 2) softmax over n (in place on q rows)
    softmax_n_kernel<<<BATCH * HID, 256>>>();
    // 3+4) fused softmax over d + partial ctx, then deterministic reduce
    ctx_part_kernel<<<BATCH * NHEADS * NCHUNK, 256>>>();
    ctx_reduce_kernel<<<65536 / 256, 256>>>();
    // 5) compose W2 = w_out o ctx
    w2_kernel<<<(BATCH * CDIM * HID) / 256, 256>>>(w_out);
    // 6) y = W2 @ q (fused attention-out + output projection)
    gemm128<<<gg, 256>>>(w2_p, qkv_p, out, HID,
                         (size_t)CDIM * HID, (size_t)256 * NPIX, (size_t)CDIM * NPIX, 128);
}

// round 3
// speedup vs baseline: 2.1899x; 1.3345x over previous
#include <cuda_runtime.h>
#include <math.h>
#include <stdint.h>

#define BATCH  16
#define CDIM   256
#define NPIX   4096
#define NHEADS 4
#define DHEAD  32
#define HID    128
#define NCHUNK 32
#define CHW    128
#define PAD    20            // smem row pitch: (20*g + t) mod 32 hits all banks

// Scratch (device globals: allocation-free per harness rules)
__device__ float g_qkv [BATCH * 256 * NPIX];                 // rows 0-127 = q, 128-255 = v
__device__ float g_ctxp[NCHUNK * BATCH * NHEADS * DHEAD * DHEAD];
__device__ float g_ctx [BATCH * NHEADS * DHEAD * DHEAD];
__device__ float g_W2  [BATCH * CDIM * HID];

__device__ __forceinline__ uint32_t f2tf32(float f)
{
    uint32_t u;
    asm("cvt.rna.tf32.f32 %0, %1;" : "=r"(u) : "f"(f));
    return u;
}

__device__ __forceinline__ void mma_tf32(float c[4],
    uint32_t a0, uint32_t a1, uint32_t a2, uint32_t a3,
    uint32_t b0, uint32_t b1)
{
    asm volatile(
        "mma.sync.aligned.m16n8k8.row.col.f32.tf32.tf32.f32 "
        "{%0,%1,%2,%3}, {%4,%5,%6,%7}, {%8,%9}, {%0,%1,%2,%3};"
        : "+f"(c[0]), "+f"(c[1]), "+f"(c[2]), "+f"(c[3])
        : "r"(a0), "r"(a1), "r"(a2), "r"(a3), "r"(b0), "r"(b1));
}

// ---------------------------------------------------------------------------
// tf32 tensor-core GEMM: C[b] = A[b](M x K row-major) * B[b](K x 4096)
// block tile 128x128, BK=16, 256 threads = 8 warps (4m x 2n), warp tile 32x64.
// ---------------------------------------------------------------------------
__global__ void __launch_bounds__(256)
gemm_tf32(const float* __restrict__ A, const float* __restrict__ B,
          float* __restrict__ C, int K,
          size_t sA, size_t sB, size_t sC, int aJump)
{
    __shared__ uint32_t As[128][PAD];   // [m][k]  tf32 bits
    __shared__ uint32_t Bs[128][PAD];   // [n][k]  tf32 bits

    int b = blockIdx.z;
    const float* Ab = A + (size_t)b * sA + (size_t)(blockIdx.y * aJump) * K;
    const float* Bb = B + (size_t)b * sB + blockIdx.x * 128;
    float*       Cb = C + (size_t)b * sC + (size_t)(blockIdx.y * 128) * NPIX + blockIdx.x * 128;

    int tid  = threadIdx.x;
    int lane = tid & 31, warp = tid >> 5;
    int g = lane >> 2, t = lane & 3;
    int wm = (warp >> 1) * 32;          // warp m-base (0,32,64,96)
    int wn = (warp & 1) * 64;           // warp n-base (0,64)

    int arow = tid >> 1, akb = (tid & 1) * 8;     // A loader: 128 rows x 16 k
    int bk   = tid >> 4, bnb = (tid & 15) * 8;    // B loader: 16 k x 128 n

    float acc[2][8][4] = {};            // [mt][nt][frag]

    for (int k0 = 0; k0 < K; k0 += 16) {
        {
            float4 a0 = *(const float4*)&Ab[(size_t)arow * K + k0 + akb];
            float4 a1 = *(const float4*)&Ab[(size_t)arow * K + k0 + akb + 4];
            As[arow][akb + 0] = f2tf32(a0.x); As[arow][akb + 1] = f2tf32(a0.y);
            As[arow][akb + 2] = f2tf32(a0.z); As[arow][akb + 3] = f2tf32(a0.w);
            As[arow][akb + 4] = f2tf32(a1.x); As[arow][akb + 5] = f2tf32(a1.y);
            As[arow][akb + 6] = f2tf32(a1.z); As[arow][akb + 7] = f2tf32(a1.w);
        }
        {
            const float* bp = &Bb[(size_t)(k0 + bk) * NPIX + bnb];
            float4 b0 = *(const float4*)&bp[0];
            float4 b1 = *(const float4*)&bp[4];
            Bs[bnb + 0][bk] = f2tf32(b0.x); Bs[bnb + 1][bk] = f2tf32(b0.y);
            Bs[bnb + 2][bk] = f2tf32(b0.z); Bs[bnb + 3][bk] = f2tf32(b0.w);
            Bs[bnb + 4][bk] = f2tf32(b1.x); Bs[bnb + 5][bk] = f2tf32(b1.y);
            Bs[bnb + 6][bk] = f2tf32(b1.z); Bs[bnb + 7][bk] = f2tf32(b1.w);
        }
        __syncthreads();

#pragma unroll
        for (int k8 = 0; k8 < 16; k8 += 8) {
            uint32_t af[2][4], bf[8][2];
#pragma unroll
            for (int mt = 0; mt < 2; mt++) {
                int r = wm + mt * 16 + g;
                af[mt][0] = As[r    ][k8 + t];
                af[mt][1] = As[r + 8][k8 + t];
                af[mt][2] = As[r    ][k8 + t + 4];
                af[mt][3] = As[r + 8][k8 + t + 4];
            }
#pragma unroll
            for (int nt = 0; nt < 8; nt++) {
                int c = wn + nt * 8 + g;
                bf[nt][0] = Bs[c][k8 + t];
                bf[nt][1] = Bs[c][k8 + t + 4];
            }
#pragma unroll
            for (int mt = 0; mt < 2; mt++)
#pragma unroll
                for (int nt = 0; nt < 8; nt++)
                    mma_tf32(acc[mt][nt],
                             af[mt][0], af[mt][1], af[mt][2], af[mt][3],
                             bf[nt][0], bf[nt][1]);
        }
        __syncthreads();
    }

#pragma unroll
    for (int mt = 0; mt < 2; mt++) {
        int r0 = wm + mt * 16 + g;
#pragma unroll
        for (int nt = 0; nt < 8; nt++) {
            int c0 = wn + nt * 8 + 2 * t;
            float2 lo = {acc[mt][nt][0], acc[mt][nt][1]};
            float2 hi = {acc[mt][nt][2], acc[mt][nt][3]};
            *(float2*)&Cb[(size_t)r0       * NPIX + c0] = lo;
            *(float2*)&Cb[(size_t)(r0 + 8) * NPIX + c0] = hi;
        }
    }
}

// ---------------------------------------------------------------------------
// Softmax over n (axis=-1), in place on q rows of g_qkv.
// ---------------------------------------------------------------------------
__global__ void softmax_n_kernel()
{
    int r = blockIdx.x;                 // 0..2047
    int b = r >> 7, q = r & 127;
    float* row = g_qkv + (size_t)b * 256 * NPIX + (size_t)q * NPIX;
    int tid = threadIdx.x;

    float v[16];
    float m = -1e30f;
#pragma unroll
    for (int i = 0; i < 16; i++) { v[i] = row[tid + i * 256]; m = fmaxf(m, v[i]); }

    __shared__ float red[8];
#pragma unroll
    for (int o = 16; o > 0; o >>= 1) m = fmaxf(m, __shfl_xor_sync(~0u, m, o));
    if ((tid & 31) == 0) red[tid >> 5] = m;
    __syncthreads();
    m = red[0];
#pragma unroll
    for (int i = 1; i < 8; i++) m = fmaxf(m, red[i]);
    __syncthreads();

    float s = 0.f;
#pragma unroll
    for (int i = 0; i < 16; i++) { v[i] = __expf(v[i] - m); s += v[i]; }
#pragma unroll
    for (int o = 16; o > 0; o >>= 1) s += __shfl_xor_sync(~0u, s, o);
    if ((tid & 31) == 0) red[tid >> 5] = s;
    __syncthreads();
    s = red[0];
#pragma unroll
    for (int i = 1; i < 8; i++) s += red[i];
    float inv = 1.0f / s;
#pragma unroll
    for (int i = 0; i < 16; i++) row[tid + i * 256] = v[i] * inv;
}

// ---------------------------------------------------------------------------
// Fused: per-column softmax over d (axis=-2) + partial context GEMM.
// ---------------------------------------------------------------------------
__global__ void ctx_part_kernel()
{
    int bid = blockIdx.x;
    int ch  = bid & 31;
    int bh  = bid >> 5;
    int b   = bh >> 2, h = bh & 3;
    int n0  = ch * CHW;

    const float* qp = g_qkv + ((size_t)b * 256 + h * DHEAD) * NPIX + n0;
    const float* vp = g_qkv + ((size_t)b * 256 + 128 + h * DHEAD) * NPIX + n0;

    __shared__ float kst[CHW][DHEAD + 1];
    __shared__ float vst[CHW][DHEAD + 1];

    int tid = threadIdx.x;

#pragma unroll
    for (int r = 0; r < 4; r++) {
        int idx = tid + r * 256;
        int row = idx >> 5;
        int col = (idx & 31) * 4;
        float4 qv = *(const float4*)&qp[(size_t)row * NPIX + col];
        kst[col + 0][row] = qv.x; kst[col + 1][row] = qv.y;
        kst[col + 2][row] = qv.z; kst[col + 3][row] = qv.w;
        float4 vv = *(const float4*)&vp[(size_t)row * NPIX + col];
        vst[col + 0][row] = vv.x; vst[col + 1][row] = vv.y;
        vst[col + 2][row] = vv.z; vst[col + 3][row] = vv.w;
    }
    __syncthreads();

    if (tid < CHW) {
        float e[DHEAD];
        float m = -1e30f;
#pragma unroll
        for (int d = 0; d < DHEAD; d++) { e[d] = kst[tid][d]; m = fmaxf(m, e[d]); }
        float s = 0.f;
#pragma unroll
        for (int d = 0; d < DHEAD; d++) { e[d] = __expf(e[d] - m); s += e[d]; }
        float inv = 1.0f / s;
#pragma unroll
        for (int d = 0; d < DHEAD; d++) kst[tid][d] = e[d] * inv;
    }
    __syncthreads();

    int tx = tid & 15, ty = tid >> 4;
    float acc[2][2] = {};
#pragma unroll 4
    for (int j = 0; j < CHW; j++) {
        float k0 = kst[j][ty * 2], k1 = kst[j][ty * 2 + 1];
        float v0 = vst[j][tx * 2], v1 = vst[j][tx * 2 + 1];
        acc[0][0] = fmaf(k0, v0, acc[0][0]);
        acc[0][1] = fmaf(k0, v1, acc[0][1]);
        acc[1][0] = fmaf(k1, v0, acc[1][0]);
        acc[1][1] = fmaf(k1, v1, acc[1][1]);
    }
    float* pp = g_ctxp + (size_t)ch * (64 * 1024) + (size_t)bh * 1024;
#pragma unroll
    for (int i = 0; i < 2; i++)
#pragma unroll
        for (int j = 0; j < 2; j++)
            pp[(ty * 2 + i) * DHEAD + tx * 2 + j] = acc[i][j];
}

__global__ void ctx_reduce_kernel()
{
    int idx = blockIdx.x * 256 + threadIdx.x;
    float s = 0.f;
#pragma unroll
    for (int ch = 0; ch < NCHUNK; ch++) s += g_ctxp[(size_t)ch * 65536 + idx];
    g_ctx[idx] = s;
}

// ---------------------------------------------------------------------------
// W2[b,o,h*32+k] = sum_v w_out[o, h*32+v] * ctx[b,h,k,v]
// ---------------------------------------------------------------------------
__global__ void w2_kernel(const float* __restrict__ w_out)
{
    int idx = blockIdx.x * 256 + threadIdx.x;
    int b   = idx >> 15;
    int rem = idx & 32767;
    int o   = rem >> 7;
    int c2  = rem & 127;
    int h   = c2 >> 5, kk = c2 & 31;

    const float* wrow = w_out + o * HID + h * DHEAD;
    const float* cp   = g_ctx + (((size_t)b * NHEADS + h) * DHEAD + kk) * DHEAD;
    float s = 0.f;
#pragma unroll
    for (int v = 0; v < 32; v++) s = fmaf(wrow[v], cp[v], s);
    g_W2[idx] = s;
}

// ---------------------------------------------------------------------------
extern "C" void kernel_launch(void* const* d_in, const int* in_sizes, int n_in,
                              void* d_out, int out_size)
{
    const float* x     = (const float*)d_in[0];
    const float* w_qkv = (const float*)d_in[1];
    const float* w_out = (const float*)d_in[2];
    float*       out   = (float*)d_out;

    float *qkv_p, *w2_p;
    cudaGetSymbolAddress((void**)&qkv_p, g_qkv);
    cudaGetSymbolAddress((void**)&w2_p,  g_W2);

    dim3 gg(NPIX / 128, 2, BATCH);

    // 1) q and v projections (tf32 tensor cores); skip unused k_proj rows
    gemm_tf32<<<gg, 256>>>(w_qkv, x, qkv_p, CDIM,
                           0, (size_t)CDIM * NPIX, (size_t)256 * NPIX, 256);
    // 2) softmax over n (in place on q rows)
    softmax_n_kernel<<<BATCH * HID, 256>>>();
    // 3+4) fused softmax over d + partial ctx, deterministic reduce
    ctx_part_kernel<<<BATCH * NHEADS * NCHUNK, 256>>>();
    ctx_reduce_kernel<<<65536 / 256, 256>>>();
    // 5) compose W2 = w_out o ctx
    w2_kernel<<<(BATCH * CDIM * HID) / 256, 256>>>(w_out);
    // 6) y = W2 @ q (tf32)
    gemm_tf32<<<gg, 256>>>(w2_p, qkv_p, out, HID,
                           (size_t)CDIM * HID, (size_t)256 * NPIX, (size_t)CDIM * NPIX, 128);
}

// round 4
// speedup vs baseline: 2.3445x; 1.0706x over previous
#include <cuda_runtime.h>
#include <math.h>
#include <stdint.h>

#define BATCH  16
#define CDIM   256
#define NPIX   4096
#define NHEADS 4
#define DHEAD  32
#define HID    128
#define NCHUNK 32
#define CHW    128
#define PAD    20            // gemm smem pitch trick
#define CPITCH 132           // ctx smem pitch: 132 % 32 == 4 -> frag banks 4g+t all distinct

// Scratch (device globals: allocation-free per harness rules)
__device__ float g_qkv [BATCH * 256 * NPIX];                 // rows 0-127 = q, 128-255 = v
__device__ float g_ctxp[NCHUNK * BATCH * NHEADS * DHEAD * DHEAD];
__device__ float g_ctx [BATCH * NHEADS * DHEAD * DHEAD];
__device__ float g_W2  [BATCH * CDIM * HID];

__device__ __forceinline__ uint32_t f2tf32(float f)
{
    uint32_t u;
    asm("cvt.rna.tf32.f32 %0, %1;" : "=r"(u) : "f"(f));
    return u;
}

__device__ __forceinline__ void mma_tf32(float c[4],
    uint32_t a0, uint32_t a1, uint32_t a2, uint32_t a3,
    uint32_t b0, uint32_t b1)
{
    asm volatile(
        "mma.sync.aligned.m16n8k8.row.col.f32.tf32.tf32.f32 "
        "{%0,%1,%2,%3}, {%4,%5,%6,%7}, {%8,%9}, {%0,%1,%2,%3};"
        : "+f"(c[0]), "+f"(c[1]), "+f"(c[2]), "+f"(c[3])
        : "r"(a0), "r"(a1), "r"(a2), "r"(a3), "r"(b0), "r"(b1));
}

// ---------------------------------------------------------------------------
// tf32 tensor-core GEMM: C[b] = A[b](M x K row-major) * B[b](K x 4096)
// block tile 128x128, BK=16, 256 threads = 8 warps (4m x 2n), warp tile 32x64.
// ---------------------------------------------------------------------------
__global__ void __launch_bounds__(256)
gemm_tf32(const float* __restrict__ A, const float* __restrict__ B,
          float* __restrict__ C, int K,
          size_t sA, size_t sB, size_t sC, int aJump)
{
    __shared__ uint32_t As[128][PAD];   // [m][k]
    __shared__ uint32_t Bs[128][PAD];   // [n][k]

    int b = blockIdx.z;
    const float* Ab = A + (size_t)b * sA + (size_t)(blockIdx.y * aJump) * K;
    const float* Bb = B + (size_t)b * sB + blockIdx.x * 128;
    float*       Cb = C + (size_t)b * sC + (size_t)(blockIdx.y * 128) * NPIX + blockIdx.x * 128;

    int tid  = threadIdx.x;
    int lane = tid & 31, warp = tid >> 5;
    int g = lane >> 2, t = lane & 3;
    int wm = (warp >> 1) * 32;
    int wn = (warp & 1) * 64;

    int arow = tid >> 1, akb = (tid & 1) * 8;
    int bk   = tid >> 4, bnb = (tid & 15) * 8;

    float acc[2][8][4] = {};

    for (int k0 = 0; k0 < K; k0 += 16) {
        {
            float4 a0 = *(const float4*)&Ab[(size_t)arow * K + k0 + akb];
            float4 a1 = *(const float4*)&Ab[(size_t)arow * K + k0 + akb + 4];
            As[arow][akb + 0] = f2tf32(a0.x); As[arow][akb + 1] = f2tf32(a0.y);
            As[arow][akb + 2] = f2tf32(a0.z); As[arow][akb + 3] = f2tf32(a0.w);
            As[arow][akb + 4] = f2tf32(a1.x); As[arow][akb + 5] = f2tf32(a1.y);
            As[arow][akb + 6] = f2tf32(a1.z); As[arow][akb + 7] = f2tf32(a1.w);
        }
        {
            const float* bp = &Bb[(size_t)(k0 + bk) * NPIX + bnb];
            float4 b0 = *(const float4*)&bp[0];
            float4 b1 = *(const float4*)&bp[4];
            Bs[bnb + 0][bk] = f2tf32(b0.x); Bs[bnb + 1][bk] = f2tf32(b0.y);
            Bs[bnb + 2][bk] = f2tf32(b0.z); Bs[bnb + 3][bk] = f2tf32(b0.w);
            Bs[bnb + 4][bk] = f2tf32(b1.x); Bs[bnb + 5][bk] = f2tf32(b1.y);
            Bs[bnb + 6][bk] = f2tf32(b1.z); Bs[bnb + 7][bk] = f2tf32(b1.w);
        }
        __syncthreads();

#pragma unroll
        for (int k8 = 0; k8 < 16; k8 += 8) {
            uint32_t af[2][4], bf[8][2];
#pragma unroll
            for (int mt = 0; mt < 2; mt++) {
                int r = wm + mt * 16 + g;
                af[mt][0] = As[r    ][k8 + t];
                af[mt][1] = As[r + 8][k8 + t];
                af[mt][2] = As[r    ][k8 + t + 4];
                af[mt][3] = As[r + 8][k8 + t + 4];
            }
#pragma unroll
            for (int nt = 0; nt < 8; nt++) {
                int c = wn + nt * 8 + g;
                bf[nt][0] = Bs[c][k8 + t];
                bf[nt][1] = Bs[c][k8 + t + 4];
            }
#pragma unroll
            for (int mt = 0; mt < 2; mt++)
#pragma unroll
                for (int nt = 0; nt < 8; nt++)
                    mma_tf32(acc[mt][nt],
                             af[mt][0], af[mt][1], af[mt][2], af[mt][3],
                             bf[nt][0], bf[nt][1]);
        }
        __syncthreads();
    }

#pragma unroll
    for (int mt = 0; mt < 2; mt++) {
        int r0 = wm + mt * 16 + g;
#pragma unroll
        for (int nt = 0; nt < 8; nt++) {
            int c0 = wn + nt * 8 + 2 * t;
            float2 lo = {acc[mt][nt][0], acc[mt][nt][1]};
            float2 hi = {acc[mt][nt][2], acc[mt][nt][3]};
            *(float2*)&Cb[(size_t)r0       * NPIX + c0] = lo;
            *(float2*)&Cb[(size_t)(r0 + 8) * NPIX + c0] = hi;
        }
    }
}

// ---------------------------------------------------------------------------
// Softmax over n (axis=-1), in place on q rows of g_qkv.
// ---------------------------------------------------------------------------
__global__ void softmax_n_kernel()
{
    int r = blockIdx.x;                 // 0..2047
    int b = r >> 7, q = r & 127;
    float* row = g_qkv + (size_t)b * 256 * NPIX + (size_t)q * NPIX;
    int tid = threadIdx.x;

    float v[16];
    float m = -1e30f;
#pragma unroll
    for (int i = 0; i < 16; i++) { v[i] = row[tid + i * 256]; m = fmaxf(m, v[i]); }

    __shared__ float red[8];
#pragma unroll
    for (int o = 16; o > 0; o >>= 1) m = fmaxf(m, __shfl_xor_sync(~0u, m, o));
    if ((tid & 31) == 0) red[tid >> 5] = m;
    __syncthreads();
    m = red[0];
#pragma unroll
    for (int i = 1; i < 8; i++) m = fmaxf(m, red[i]);
    __syncthreads();

    float s = 0.f;
#pragma unroll
    for (int i = 0; i < 16; i++) { v[i] = __expf(v[i] - m); s += v[i]; }
#pragma unroll
    for (int o = 16; o > 0; o >>= 1) s += __shfl_xor_sync(~0u, s, o);
    if ((tid & 31) == 0) red[tid >> 5] = s;
    __syncthreads();
    s = red[0];
#pragma unroll
    for (int i = 1; i < 8; i++) s += red[i];
    float inv = 1.0f / s;
#pragma unroll
    for (int i = 0; i < 16; i++) row[tid + i * 256] = v[i] * inv;
}

// ---------------------------------------------------------------------------
// Fused: per-column softmax over d (axis=-2) + partial context via tf32 MMA.
// One block per (b, h, n-chunk of 128). Tiles in natural [d][n] layout,
// pitch 132 (132%32==4 -> fragment addr bank = 4g+t : conflict-free).
// partial[ch][b,h][k,v] = sum_{n in chunk} softmax_d(q)[k,n] * v[v,n]
// ---------------------------------------------------------------------------
__global__ void __launch_bounds__(256) ctx_part_kernel()
{
    int bid = blockIdx.x;               // 0..2047
    int ch  = bid & 31;
    int bh  = bid >> 5;
    int b   = bh >> 2, h = bh & 3;
    int n0  = ch * CHW;

    const float* qp = g_qkv + ((size_t)b * 256 + h * DHEAD) * NPIX + n0;
    const float* vp = g_qkv + ((size_t)b * 256 + 128 + h * DHEAD) * NPIX + n0;

    __shared__ float kst[DHEAD][CPITCH];    // [d][n]  (k after softmax_d)
    __shared__ float vst[DHEAD][CPITCH];    // [d][n]

    int tid = threadIdx.x;

    // coalesced load, no transpose: 32 rows x 128 cols, float4
#pragma unroll
    for (int r = 0; r < 4; r++) {
        int idx = tid + r * 256;        // 0..1023
        int row = idx >> 5;             // d
        int col = (idx & 31) * 4;       // n
        *(float4*)&kst[row][col] = *(const float4*)&qp[(size_t)row * NPIX + col];
        *(float4*)&vst[row][col] = *(const float4*)&vp[(size_t)row * NPIX + col];
    }
    __syncthreads();

    // per-column softmax over d: thread tid<128 owns column n=tid (conflict-free)
    if (tid < CHW) {
        float e[DHEAD];
        float m = -1e30f;
#pragma unroll
        for (int d = 0; d < DHEAD; d++) { e[d] = kst[d][tid]; m = fmaxf(m, e[d]); }
        float s = 0.f;
#pragma unroll
        for (int d = 0; d < DHEAD; d++) { e[d] = __expf(e[d] - m); s += e[d]; }
        float inv = 1.0f / s;
#pragma unroll
        for (int d = 0; d < DHEAD; d++) kst[d][tid] = e[d] * inv;
    }
    __syncthreads();

    // MMA: ctx[32k x 32v] += k[32 x 128n] * v[32 x 128n]^T
    // 8 warps: warp w -> tile (mt = w>>2 of 16 rows, nt = w&3 of 8 cols)
    int lane = tid & 31, warp = tid >> 5;
    int g = lane >> 2, t = lane & 3;
    int mrow = (warp >> 2) * 16;        // 0 or 16
    int ncol = (warp & 3) * 8;          // 0,8,16,24

    float acc[4] = {};
#pragma unroll
    for (int k8 = 0; k8 < CHW; k8 += 8) {
        uint32_t a0 = __float_as_uint(kst[mrow + g    ][k8 + t]);
        uint32_t a1 = __float_as_uint(kst[mrow + g + 8][k8 + t]);
        uint32_t a2 = __float_as_uint(kst[mrow + g    ][k8 + t + 4]);
        uint32_t a3 = __float_as_uint(kst[mrow + g + 8][k8 + t + 4]);
        uint32_t b0 = __float_as_uint(vst[ncol + g][k8 + t]);
        uint32_t b1 = __float_as_uint(vst[ncol + g][k8 + t + 4]);
        // quantize to tf32 (mma requires tf32-format operands)
        a0 = f2tf32(__uint_as_float(a0)); a1 = f2tf32(__uint_as_float(a1));
        a2 = f2tf32(__uint_as_float(a2)); a3 = f2tf32(__uint_as_float(a3));
        b0 = f2tf32(__uint_as_float(b0)); b1 = f2tf32(__uint_as_float(b1));
        mma_tf32(acc, a0, a1, a2, a3, b0, b1);
    }

    float* pp = g_ctxp + (size_t)ch * (64 * 1024) + (size_t)bh * 1024;
    float2 lo = {acc[0], acc[1]};
    float2 hi = {acc[2], acc[3]};
    *(float2*)&pp[(mrow + g    ) * DHEAD + ncol + 2 * t] = lo;
    *(float2*)&pp[(mrow + g + 8) * DHEAD + ncol + 2 * t] = hi;
}

__global__ void ctx_reduce_kernel()
{
    int idx = blockIdx.x * 256 + threadIdx.x;
    float s = 0.f;
#pragma unroll
    for (int ch = 0; ch < NCHUNK; ch++) s += g_ctxp[(size_t)ch * 65536 + idx];
    g_ctx[idx] = s;
}

// ---------------------------------------------------------------------------
// W2[b,o,h*32+k] = sum_v w_out[o, h*32+v] * ctx[b,h,k,v]
// ---------------------------------------------------------------------------
__global__ void w2_kernel(const float* __restrict__ w_out)
{
    int idx = blockIdx.x * 256 + threadIdx.x;
    int b   = idx >> 15;
    int rem = idx & 32767;
    int o   = rem >> 7;
    int c2  = rem & 127;
    int h   = c2 >> 5, kk = c2 & 31;

    const float* wrow = w_out + o * HID + h * DHEAD;
    const float* cp   = g_ctx + (((size_t)b * NHEADS + h) * DHEAD + kk) * DHEAD;
    float s = 0.f;
#pragma unroll
    for (int v = 0; v < 32; v++) s = fmaf(wrow[v], cp[v], s);
    g_W2[idx] = s;
}

// ---------------------------------------------------------------------------
extern "C" void kernel_launch(void* const* d_in, const int* in_sizes, int n_in,
                              void* d_out, int out_size)
{
    const float* x     = (const float*)d_in[0];
    const float* w_qkv = (const float*)d_in[1];
    const float* w_out = (const float*)d_in[2];
    float*       out   = (float*)d_out;

    float *qkv_p, *w2_p;
    cudaGetSymbolAddress((void**)&qkv_p, g_qkv);
    cudaGetSymbolAddress((void**)&w2_p,  g_W2);

    dim3 gg(NPIX / 128, 2, BATCH);

    // 1) q and v projections (tf32 tensor cores); skip unused k_proj rows
    gemm_tf32<<<gg, 256>>>(w_qkv, x, qkv_p, CDIM,
                           0, (size_t)CDIM * NPIX, (size_t)256 * NPIX, 256);
    // 2) softmax over n (in place on q rows)
    softmax_n_kernel<<<BATCH * HID, 256>>>();
    // 3+4) fused softmax over d + partial ctx (tf32 MMA), deterministic reduce
    ctx_part_kernel<<<BATCH * NHEADS * NCHUNK, 256>>>();
    ctx_reduce_kernel<<<65536 / 256, 256>>>();
    // 5) compose W2 = w_out o ctx
    w2_kernel<<<(BATCH * CDIM * HID) / 256, 256>>>(w_out);
    // 6) y = W2 @ q (tf32)
    gemm_tf32<<<gg, 256>>>(w2_p, qkv_p, out, HID,
                           (size_t)CDIM * HID, (size_t)256 * NPIX, (size_t)CDIM * NPIX, 128);
}

// round 5
// speedup vs baseline: 2.5259x; 1.0774x over previous
#include <cuda_runtime.h>
#include <math.h>
#include <stdint.h>

#define BATCH  16
#define CDIM   256
#define NPIX   4096
#define NHEADS 4
#define DHEAD  32
#define HID    128
#define NCHUNK 32
#define CHW    128
#define PAD    20            // gemm smem pitch: frag bank = (20g+t)%32, all distinct
#define CPITCH 132           // ctx smem pitch: 132 % 32 == 4 -> frag banks 4g+t all distinct

// Scratch (device globals: allocation-free per harness rules)
__device__ float g_qkv [BATCH * 256 * NPIX];                 // rows 0-127 = q, 128-255 = v
__device__ float g_ctxp[NCHUNK * BATCH * NHEADS * DHEAD * DHEAD];
__device__ float g_ctx [BATCH * NHEADS * DHEAD * DHEAD];
__device__ float g_W2  [BATCH * CDIM * HID];

__device__ __forceinline__ uint32_t f2tf32(float f)
{
    uint32_t u;
    asm("cvt.rna.tf32.f32 %0, %1;" : "=r"(u) : "f"(f));
    return u;
}

__device__ __forceinline__ void mma_tf32(float c[4],
    uint32_t a0, uint32_t a1, uint32_t a2, uint32_t a3,
    uint32_t b0, uint32_t b1)
{
    asm volatile(
        "mma.sync.aligned.m16n8k8.row.col.f32.tf32.tf32.f32 "
        "{%0,%1,%2,%3}, {%4,%5,%6,%7}, {%8,%9}, {%0,%1,%2,%3};"
        : "+f"(c[0]), "+f"(c[1]), "+f"(c[2]), "+f"(c[3])
        : "r"(a0), "r"(a1), "r"(a2), "r"(a3), "r"(b0), "r"(b1));
}

// ---------------------------------------------------------------------------
// tf32 tensor-core GEMM, double-buffered software pipeline.
// C[b] = A[b](M x K row-major) * B[b](K x 4096); block tile 128x128, BK=16,
// 256 threads = 8 warps (4m x 2n), warp tile 32x64.
// ---------------------------------------------------------------------------
__global__ void __launch_bounds__(256)
gemm_tf32(const float* __restrict__ A, const float* __restrict__ B,
          float* __restrict__ C, int K,
          size_t sA, size_t sB, size_t sC, int aJump)
{
    __shared__ uint32_t As[2][128][PAD];   // [buf][m][k]
    __shared__ uint32_t Bs[2][128][PAD];   // [buf][n][k]

    int b = blockIdx.z;
    const float* Ab = A + (size_t)b * sA + (size_t)(blockIdx.y * aJump) * K;
    const float* Bb = B + (size_t)b * sB + blockIdx.x * 128;
    float*       Cb = C + (size_t)b * sC + (size_t)(blockIdx.y * 128) * NPIX + blockIdx.x * 128;

    int tid  = threadIdx.x;
    int lane = tid & 31, warp = tid >> 5;
    int g = lane >> 2, t = lane & 3;
    int wm = (warp >> 1) * 32;
    int wn = (warp & 1) * 64;

    int arow = tid >> 1, akb = (tid & 1) * 8;     // A loader: 128 rows x 16 k
    int bk   = tid >> 4, bnb = (tid & 15) * 8;    // B loader: 16 k x 128 n

    const float* aPtr = &Ab[(size_t)arow * K + akb];
    const float* bPtr = &Bb[(size_t)bk * NPIX + bnb];

    float acc[2][8][4] = {};
    float4 ra0, ra1, rb0, rb1;

    // prologue: load tile 0
    ra0 = *(const float4*)&aPtr[0];
    ra1 = *(const float4*)&aPtr[4];
    rb0 = *(const float4*)&bPtr[0];
    rb1 = *(const float4*)&bPtr[4];
    {
        As[0][arow][akb + 0] = f2tf32(ra0.x); As[0][arow][akb + 1] = f2tf32(ra0.y);
        As[0][arow][akb + 2] = f2tf32(ra0.z); As[0][arow][akb + 3] = f2tf32(ra0.w);
        As[0][arow][akb + 4] = f2tf32(ra1.x); As[0][arow][akb + 5] = f2tf32(ra1.y);
        As[0][arow][akb + 6] = f2tf32(ra1.z); As[0][arow][akb + 7] = f2tf32(ra1.w);
        Bs[0][bnb + 0][bk] = f2tf32(rb0.x); Bs[0][bnb + 1][bk] = f2tf32(rb0.y);
        Bs[0][bnb + 2][bk] = f2tf32(rb0.z); Bs[0][bnb + 3][bk] = f2tf32(rb0.w);
        Bs[0][bnb + 4][bk] = f2tf32(rb1.x); Bs[0][bnb + 5][bk] = f2tf32(rb1.y);
        Bs[0][bnb + 6][bk] = f2tf32(rb1.z); Bs[0][bnb + 7][bk] = f2tf32(rb1.w);
    }
    __syncthreads();

    int nsteps = K >> 4;
    for (int s = 0; s < nsteps; s++) {
        int cur = s & 1;
        int has_next = (s + 1 < nsteps);

        // issue next tile's gmem loads (overlap with MMA below)
        if (has_next) {
            const float* ap = aPtr + (s + 1) * 16;
            const float* bp = bPtr + (size_t)(s + 1) * 16 * NPIX;
            ra0 = *(const float4*)&ap[0];
            ra1 = *(const float4*)&ap[4];
            rb0 = *(const float4*)&bp[0];
            rb1 = *(const float4*)&bp[4];
        }

        // compute on buffer cur
#pragma unroll
        for (int k8 = 0; k8 < 16; k8 += 8) {
            uint32_t af[2][4], bf[8][2];
#pragma unroll
            for (int mt = 0; mt < 2; mt++) {
                int r = wm + mt * 16 + g;
                af[mt][0] = As[cur][r    ][k8 + t];
                af[mt][1] = As[cur][r + 8][k8 + t];
                af[mt][2] = As[cur][r    ][k8 + t + 4];
                af[mt][3] = As[cur][r + 8][k8 + t + 4];
            }
#pragma unroll
            for (int nt = 0; nt < 8; nt++) {
                int c = wn + nt * 8 + g;
                bf[nt][0] = Bs[cur][c][k8 + t];
                bf[nt][1] = Bs[cur][c][k8 + t + 4];
            }
#pragma unroll
            for (int mt = 0; mt < 2; mt++)
#pragma unroll
                for (int nt = 0; nt < 8; nt++)
                    mma_tf32(acc[mt][nt],
                             af[mt][0], af[mt][1], af[mt][2], af[mt][3],
                             bf[nt][0], bf[nt][1]);
        }

        // stage next tile into the other buffer
        if (has_next) {
            int nxt = cur ^ 1;
            As[nxt][arow][akb + 0] = f2tf32(ra0.x); As[nxt][arow][akb + 1] = f2tf32(ra0.y);
            As[nxt][arow][akb + 2] = f2tf32(ra0.z); As[nxt][arow][akb + 3] = f2tf32(ra0.w);
            As[nxt][arow][akb + 4] = f2tf32(ra1.x); As[nxt][arow][akb + 5] = f2tf32(ra1.y);
            As[nxt][arow][akb + 6] = f2tf32(ra1.z); As[nxt][arow][akb + 7] = f2tf32(ra1.w);
            Bs[nxt][bnb + 0][bk] = f2tf32(rb0.x); Bs[nxt][bnb + 1][bk] = f2tf32(rb0.y);
            Bs[nxt][bnb + 2][bk] = f2tf32(rb0.z); Bs[nxt][bnb + 3][bk] = f2tf32(rb0.w);
            Bs[nxt][bnb + 4][bk] = f2tf32(rb1.x); Bs[nxt][bnb + 5][bk] = f2tf32(rb1.y);
            Bs[nxt][bnb + 6][bk] = f2tf32(rb1.z); Bs[nxt][bnb + 7][bk] = f2tf32(rb1.w);
            __syncthreads();
        }
    }

#pragma unroll
    for (int mt = 0; mt < 2; mt++) {
        int r0 = wm + mt * 16 + g;
#pragma unroll
        for (int nt = 0; nt < 8; nt++) {
            int c0 = wn + nt * 8 + 2 * t;
            float2 lo = {acc[mt][nt][0], acc[mt][nt][1]};
            float2 hi = {acc[mt][nt][2], acc[mt][nt][3]};
            *(float2*)&Cb[(size_t)r0       * NPIX + c0] = lo;
            *(float2*)&Cb[(size_t)(r0 + 8) * NPIX + c0] = hi;
        }
    }
}

// ---------------------------------------------------------------------------
// Softmax over n (axis=-1), in place on q rows of g_qkv.
// ---------------------------------------------------------------------------
__global__ void softmax_n_kernel()
{
    int r = blockIdx.x;                 // 0..2047
    int b = r >> 7, q = r & 127;
    float* row = g_qkv + (size_t)b * 256 * NPIX + (size_t)q * NPIX;
    int tid = threadIdx.x;

    float v[16];
    float m = -1e30f;
#pragma unroll
    for (int i = 0; i < 16; i++) { v[i] = row[tid + i * 256]; m = fmaxf(m, v[i]); }

    __shared__ float red[8];
#pragma unroll
    for (int o = 16; o > 0; o >>= 1) m = fmaxf(m, __shfl_xor_sync(~0u, m, o));
    if ((tid & 31) == 0) red[tid >> 5] = m;
    __syncthreads();
    m = red[0];
#pragma unroll
    for (int i = 1; i < 8; i++) m = fmaxf(m, red[i]);
    __syncthreads();

    float s = 0.f;
#pragma unroll
    for (int i = 0; i < 16; i++) { v[i] = __expf(v[i] - m); s += v[i]; }
#pragma unroll
    for (int o = 16; o > 0; o >>= 1) s += __shfl_xor_sync(~0u, s, o);
    if ((tid & 31) == 0) red[tid >> 5] = s;
    __syncthreads();
    s = red[0];
#pragma unroll
    for (int i = 1; i < 8; i++) s += red[i];
    float inv = 1.0f / s;
#pragma unroll
    for (int i = 0; i < 16; i++) row[tid + i * 256] = v[i] * inv;
}

// ---------------------------------------------------------------------------
// Fused: per-column softmax over d (axis=-2) + partial context via tf32 MMA.
// ---------------------------------------------------------------------------
__global__ void __launch_bounds__(256) ctx_part_kernel()
{
    int bid = blockIdx.x;
    int ch  = bid & 31;
    int bh  = bid >> 5;
    int b   = bh >> 2, h = bh & 3;
    int n0  = ch * CHW;

    const float* qp = g_qkv + ((size_t)b * 256 + h * DHEAD) * NPIX + n0;
    const float* vp = g_qkv + ((size_t)b * 256 + 128 + h * DHEAD) * NPIX + n0;

    __shared__ float kst[DHEAD][CPITCH];
    __shared__ float vst[DHEAD][CPITCH];

    int tid = threadIdx.x;

#pragma unroll
    for (int r = 0; r < 4; r++) {
        int idx = tid + r * 256;
        int row = idx >> 5;
        int col = (idx & 31) * 4;
        *(float4*)&kst[row][col] = *(const float4*)&qp[(size_t)row * NPIX + col];
        *(float4*)&vst[row][col] = *(const float4*)&vp[(size_t)row * NPIX + col];
    }
    __syncthreads();

    if (tid < CHW) {
        float e[DHEAD];
        float m = -1e30f;
#pragma unroll
        for (int d = 0; d < DHEAD; d++) { e[d] = kst[d][tid]; m = fmaxf(m, e[d]); }
        float s = 0.f;
#pragma unroll
        for (int d = 0; d < DHEAD; d++) { e[d] = __expf(e[d] - m); s += e[d]; }
        float inv = 1.0f / s;
#pragma unroll
        for (int d = 0; d < DHEAD; d++) kst[d][tid] = e[d] * inv;
    }
    __syncthreads();

    int lane = tid & 31, warp = tid >> 5;
    int g = lane >> 2, t = lane & 3;
    int mrow = (warp >> 2) * 16;
    int ncol = (warp & 3) * 8;

    float acc[4] = {};
#pragma unroll
    for (int k8 = 0; k8 < CHW; k8 += 8) {
        uint32_t a0 = f2tf32(kst[mrow + g    ][k8 + t]);
        uint32_t a1 = f2tf32(kst[mrow + g + 8][k8 + t]);
        uint32_t a2 = f2tf32(kst[mrow + g    ][k8 + t + 4]);
        uint32_t a3 = f2tf32(kst[mrow + g + 8][k8 + t + 4]);
        uint32_t b0 = f2tf32(vst[ncol + g][k8 + t]);
        uint32_t b1 = f2tf32(vst[ncol + g][k8 + t + 4]);
        mma_tf32(acc, a0, a1, a2, a3, b0, b1);
    }

    float* pp = g_ctxp + (size_t)ch * (64 * 1024) + (size_t)bh * 1024;
    float2 lo = {acc[0], acc[1]};
    float2 hi = {acc[2], acc[3]};
    *(float2*)&pp[(mrow + g    ) * DHEAD + ncol + 2 * t] = lo;
    *(float2*)&pp[(mrow + g + 8) * DHEAD + ncol + 2 * t] = hi;
}

__global__ void ctx_reduce_kernel()
{
    int idx = blockIdx.x * 256 + threadIdx.x;
    float s = 0.f;
#pragma unroll
    for (int ch = 0; ch < NCHUNK; ch++) s += g_ctxp[(size_t)ch * 65536 + idx];
    g_ctx[idx] = s;
}

// ---------------------------------------------------------------------------
// W2[b,o,h*32+k] = sum_v w_out[o, h*32+v] * ctx[b,h,k,v]
// ---------------------------------------------------------------------------
__global__ void w2_kernel(const float* __restrict__ w_out)
{
    int idx = blockIdx.x * 256 + threadIdx.x;
    int b   = idx >> 15;
    int rem = idx & 32767;
    int o   = rem >> 7;
    int c2  = rem & 127;
    int h   = c2 >> 5, kk = c2 & 31;

    const float* wrow = w_out + o * HID + h * DHEAD;
    const float* cp   = g_ctx + (((size_t)b * NHEADS + h) * DHEAD + kk) * DHEAD;
    float s = 0.f;
#pragma unroll
    for (int v = 0; v < 32; v++) s = fmaf(wrow[v], cp[v], s);
    g_W2[idx] = s;
}

// ---------------------------------------------------------------------------
extern "C" void kernel_launch(void* const* d_in, const int* in_sizes, int n_in,
                              void* d_out, int out_size)
{
    const float* x     = (const float*)d_in[0];
    const float* w_qkv = (const float*)d_in[1];
    const float* w_out = (const float*)d_in[2];
    float*       out   = (float*)d_out;

    float *qkv_p, *w2_p;
    cudaGetSymbolAddress((void**)&qkv_p, g_qkv);
    cudaGetSymbolAddress((void**)&w2_p,  g_W2);

    dim3 gg(NPIX / 128, 2, BATCH);

    // 1) q and v projections (tf32 tensor cores, pipelined)
    gemm_tf32<<<gg, 256>>>(w_qkv, x, qkv_p, CDIM,
                           0, (size_t)CDIM * NPIX, (size_t)256 * NPIX, 256);
    // 2) softmax over n (in place on q rows)
    softmax_n_kernel<<<BATCH * HID, 256>>>();
    // 3+4) fused softmax over d + partial ctx (tf32 MMA), deterministic reduce
    ctx_part_kernel<<<BATCH * NHEADS * NCHUNK, 256>>>();
    ctx_reduce_kernel<<<65536 / 256, 256>>>();
    // 5) compose W2 = w_out o ctx
    w2_kernel<<<(BATCH * CDIM * HID) / 256, 256>>>(w_out);
    // 6) y = W2 @ q (tf32, pipelined)
    gemm_tf32<<<gg, 256>>>(w2_p, qkv_p, out, HID,
                           (size_t)CDIM * HID, (size_t)256 * NPIX, (size_t)CDIM * NPIX, 128);
}

// round 6
// speedup vs baseline: 3.3661x; 1.3327x over previous
#include <cuda_runtime.h>
#include <math.h>
#include <stdint.h>

#define BATCH  16
#define CDIM   256
#define NPIX   4096
#define NHEADS 4
#define DHEAD  32
#define HID    128
#define NCHUNK 32
#define CHW    128
#define PAD    20            // As pitch: frag bank = (20g+t)%32, all 32 distinct
#define BPITCH 136           // Bs pitch: 136%32==8 -> frag bank = 8t+g, all 32 distinct
#define CPITCH 132           // ctx smem pitch

// Scratch (device globals: allocation-free per harness rules)
__device__ float g_qkv [BATCH * 256 * NPIX];                 // rows 0-127 = q, 128-255 = v
__device__ float g_ctxp[NCHUNK * BATCH * NHEADS * DHEAD * DHEAD];
__device__ float g_ctx [BATCH * NHEADS * DHEAD * DHEAD];
__device__ float g_W2  [BATCH * CDIM * HID];

__device__ __forceinline__ uint32_t f2tf32(float f)
{
    uint32_t u;
    asm("cvt.rna.tf32.f32 %0, %1;" : "=r"(u) : "f"(f));
    return u;
}

__device__ __forceinline__ void mma_tf32(float c[4],
    uint32_t a0, uint32_t a1, uint32_t a2, uint32_t a3,
    uint32_t b0, uint32_t b1)
{
    asm volatile(
        "mma.sync.aligned.m16n8k8.row.col.f32.tf32.tf32.f32 "
        "{%0,%1,%2,%3}, {%4,%5,%6,%7}, {%8,%9}, {%0,%1,%2,%3};"
        : "+f"(c[0]), "+f"(c[1]), "+f"(c[2]), "+f"(c[3])
        : "r"(a0), "r"(a1), "r"(a2), "r"(a3), "r"(b0), "r"(b1));
}

__device__ __forceinline__ uint4 cvt4(float4 v)
{
    uint4 u;
    u.x = f2tf32(v.x); u.y = f2tf32(v.y); u.z = f2tf32(v.z); u.w = f2tf32(v.w);
    return u;
}

// ---------------------------------------------------------------------------
// tf32 tensor-core GEMM, double-buffered, conflict-free smem stores.
// C[b] = A[b](M x K row-major) * B[b](K x 4096); block tile 128x128, BK=16,
// 256 threads = 8 warps (4m x 2n), warp tile 32x64.
// As: [m][k] pitch 20 (STS.128 along k; frag reads bank 20g+t, distinct).
// Bs: [k][n] pitch 136 (STS.128 along n, full-width wavefronts;
//     frag reads bank 8t+g, distinct).
// ---------------------------------------------------------------------------
__global__ void __launch_bounds__(256)
gemm_tf32(const float* __restrict__ A, const float* __restrict__ B,
          float* __restrict__ C, int K,
          size_t sA, size_t sB, size_t sC, int aJump)
{
    __shared__ uint32_t As[2][128][PAD];      // [buf][m][k]
    __shared__ uint32_t Bs[2][16][BPITCH];    // [buf][k][n]

    int b = blockIdx.z;
    const float* Ab = A + (size_t)b * sA + (size_t)(blockIdx.y * aJump) * K;
    const float* Bb = B + (size_t)b * sB + blockIdx.x * 128;
    float*       Cb = C + (size_t)b * sC + (size_t)(blockIdx.y * 128) * NPIX + blockIdx.x * 128;

    int tid  = threadIdx.x;
    int lane = tid & 31, warp = tid >> 5;
    int g = lane >> 2, t = lane & 3;
    int wm = (warp >> 1) * 32;
    int wn = (warp & 1) * 64;

    int arow = tid >> 1, akb = (tid & 1) * 8;     // A loader: 128 rows x 16 k
    int bk   = tid >> 4, bnb = (tid & 15) * 8;    // B loader: 16 k x 128 n

    const float* aPtr = &Ab[(size_t)arow * K + akb];
    const float* bPtr = &Bb[(size_t)bk * NPIX + bnb];

    float acc[2][8][4] = {};
    float4 ra0, ra1, rb0, rb1;

    // prologue: load + stage tile 0
    ra0 = *(const float4*)&aPtr[0];
    ra1 = *(const float4*)&aPtr[4];
    rb0 = *(const float4*)&bPtr[0];
    rb1 = *(const float4*)&bPtr[4];
    *(uint4*)&As[0][arow][akb]     = cvt4(ra0);
    *(uint4*)&As[0][arow][akb + 4] = cvt4(ra1);
    *(uint4*)&Bs[0][bk][bnb]       = cvt4(rb0);
    *(uint4*)&Bs[0][bk][bnb + 4]   = cvt4(rb1);
    __syncthreads();

    int nsteps = K >> 4;
    for (int s = 0; s < nsteps; s++) {
        int cur = s & 1;
        int has_next = (s + 1 < nsteps);

        // issue next tile's gmem loads (overlap with MMA below)
        if (has_next) {
            const float* ap = aPtr + (s + 1) * 16;
            const float* bp = bPtr + (size_t)(s + 1) * 16 * NPIX;
            ra0 = *(const float4*)&ap[0];
            ra1 = *(const float4*)&ap[4];
            rb0 = *(const float4*)&bp[0];
            rb1 = *(const float4*)&bp[4];
        }

        // compute on buffer cur
#pragma unroll
        for (int k8 = 0; k8 < 16; k8 += 8) {
            uint32_t af[2][4], bf[8][2];
#pragma unroll
            for (int mt = 0; mt < 2; mt++) {
                int r = wm + mt * 16 + g;
                af[mt][0] = As[cur][r    ][k8 + t];
                af[mt][1] = As[cur][r + 8][k8 + t];
                af[mt][2] = As[cur][r    ][k8 + t + 4];
                af[mt][3] = As[cur][r + 8][k8 + t + 4];
            }
#pragma unroll
            for (int nt = 0; nt < 8; nt++) {
                int c = wn + nt * 8 + g;
                bf[nt][0] = Bs[cur][k8 + t    ][c];
                bf[nt][1] = Bs[cur][k8 + t + 4][c];
            }
#pragma unroll
            for (int mt = 0; mt < 2; mt++)
#pragma unroll
                for (int nt = 0; nt < 8; nt++)
                    mma_tf32(acc[mt][nt],
                             af[mt][0], af[mt][1], af[mt][2], af[mt][3],
                             bf[nt][0], bf[nt][1]);
        }

        // stage next tile into the other buffer
        if (has_next) {
            int nxt = cur ^ 1;
            *(uint4*)&As[nxt][arow][akb]     = cvt4(ra0);
            *(uint4*)&As[nxt][arow][akb + 4] = cvt4(ra1);
            *(uint4*)&Bs[nxt][bk][bnb]       = cvt4(rb0);
            *(uint4*)&Bs[nxt][bk][bnb + 4]   = cvt4(rb1);
            __syncthreads();
        }
    }

#pragma unroll
    for (int mt = 0; mt < 2; mt++) {
        int r0 = wm + mt * 16 + g;
#pragma unroll
        for (int nt = 0; nt < 8; nt++) {
            int c0 = wn + nt * 8 + 2 * t;
            float2 lo = {acc[mt][nt][0], acc[mt][nt][1]};
            float2 hi = {acc[mt][nt][2], acc[mt][nt][3]};
            *(float2*)&Cb[(size_t)r0       * NPIX + c0] = lo;
            *(float2*)&Cb[(size_t)(r0 + 8) * NPIX + c0] = hi;
        }
    }
}

// ---------------------------------------------------------------------------
// Softmax over n (axis=-1), in place on q rows of g_qkv.
// ---------------------------------------------------------------------------
__global__ void softmax_n_kernel()
{
    int r = blockIdx.x;                 // 0..2047
    int b = r >> 7, q = r & 127;
    float* row = g_qkv + (size_t)b * 256 * NPIX + (size_t)q * NPIX;
    int tid = threadIdx.x;

    float v[16];
    float m = -1e30f;
#pragma unroll
    for (int i = 0; i < 16; i++) { v[i] = row[tid + i * 256]; m = fmaxf(m, v[i]); }

    __shared__ float red[8];
#pragma unroll
    for (int o = 16; o > 0; o >>= 1) m = fmaxf(m, __shfl_xor_sync(~0u, m, o));
    if ((tid & 31) == 0) red[tid >> 5] = m;
    __syncthreads();
    m = red[0];
#pragma unroll
    for (int i = 1; i < 8; i++) m = fmaxf(m, red[i]);
    __syncthreads();

    float s = 0.f;
#pragma unroll
    for (int i = 0; i < 16; i++) { v[i] = __expf(v[i] - m); s += v[i]; }
#pragma unroll
    for (int o = 16; o > 0; o >>= 1) s += __shfl_xor_sync(~0u, s, o);
    if ((tid & 31) == 0) red[tid >> 5] = s;
    __syncthreads();
    s = red[0];
#pragma unroll
    for (int i = 1; i < 8; i++) s += red[i];
    float inv = 1.0f / s;
#pragma unroll
    for (int i = 0; i < 16; i++) row[tid + i * 256] = v[i] * inv;
}

// ---------------------------------------------------------------------------
// Fused: per-column softmax over d (axis=-2) + partial context via tf32 MMA.
// ---------------------------------------------------------------------------
__global__ void __launch_bounds__(256) ctx_part_kernel()
{
    int bid = blockIdx.x;
    int ch  = bid & 31;
    int bh  = bid >> 5;
    int b   = bh >> 2, h = bh & 3;
    int n0  = ch * CHW;

    const float* qp = g_qkv + ((size_t)b * 256 + h * DHEAD) * NPIX + n0;
    const float* vp = g_qkv + ((size_t)b * 256 + 128 + h * DHEAD) * NPIX + n0;

    __shared__ float kst[DHEAD][CPITCH];
    __shared__ float vst[DHEAD][CPITCH];

    int tid = threadIdx.x;

#pragma unroll
    for (int r = 0; r < 4; r++) {
        int idx = tid + r * 256;
        int row = idx >> 5;
        int col = (idx & 31) * 4;
        *(float4*)&kst[row][col] = *(const float4*)&qp[(size_t)row * NPIX + col];
        *(float4*)&vst[row][col] = *(const float4*)&vp[(size_t)row * NPIX + col];
    }
    __syncthreads();

    if (tid < CHW) {
        float e[DHEAD];
        float m = -1e30f;
#pragma unroll
        for (int d = 0; d < DHEAD; d++) { e[d] = kst[d][tid]; m = fmaxf(m, e[d]); }
        float s = 0.f;
#pragma unroll
        for (int d = 0; d < DHEAD; d++) { e[d] = __expf(e[d] - m); s += e[d]; }
        float inv = 1.0f / s;
#pragma unroll
        for (int d = 0; d < DHEAD; d++) kst[d][tid] = e[d] * inv;
    }
    __syncthreads();

    int lane = tid & 31, warp = tid >> 5;
    int g = lane >> 2, t = lane & 3;
    int mrow = (warp >> 2) * 16;
    int ncol = (warp & 3) * 8;

    float acc[4] = {};
#pragma unroll
    for (int k8 = 0; k8 < CHW; k8 += 8) {
        uint32_t a0 = f2tf32(kst[mrow + g    ][k8 + t]);
        uint32_t a1 = f2tf32(kst[mrow + g + 8][k8 + t]);
        uint32_t a2 = f2tf32(kst[mrow + g    ][k8 + t + 4]);
        uint32_t a3 = f2tf32(kst[mrow + g + 8][k8 + t + 4]);
        uint32_t b0 = f2tf32(vst[ncol + g][k8 + t]);
        uint32_t b1 = f2tf32(vst[ncol + g][k8 + t + 4]);
        mma_tf32(acc, a0, a1, a2, a3, b0, b1);
    }

    float* pp = g_ctxp + (size_t)ch * (64 * 1024) + (size_t)bh * 1024;
    float2 lo = {acc[0], acc[1]};
    float2 hi = {acc[2], acc[3]};
    *(float2*)&pp[(mrow + g    ) * DHEAD + ncol + 2 * t] = lo;
    *(float2*)&pp[(mrow + g + 8) * DHEAD + ncol + 2 * t] = hi;
}

__global__ void ctx_reduce_kernel()
{
    int idx = blockIdx.x * 256 + threadIdx.x;
    float s = 0.f;
#pragma unroll
    for (int ch = 0; ch < NCHUNK; ch++) s += g_ctxp[(size_t)ch * 65536 + idx];
    g_ctx[idx] = s;
}

// ---------------------------------------------------------------------------
// W2[b,o,h*32+k] = sum_v w_out[o, h*32+v] * ctx[b,h,k,v]
// ---------------------------------------------------------------------------
__global__ void w2_kernel(const float* __restrict__ w_out)
{
    int idx = blockIdx.x * 256 + threadIdx.x;
    int b   = idx >> 15;
    int rem = idx & 32767;
    int o   = rem >> 7;
    int c2  = rem & 127;
    int h   = c2 >> 5, kk = c2 & 31;

    const float* wrow = w_out + o * HID + h * DHEAD;
    const float* cp   = g_ctx + (((size_t)b * NHEADS + h) * DHEAD + kk) * DHEAD;
    float s = 0.f;
#pragma unroll
    for (int v = 0; v < 32; v++) s = fmaf(wrow[v], cp[v], s);
    g_W2[idx] = s;
}

// ---------------------------------------------------------------------------
extern "C" void kernel_launch(void* const* d_in, const int* in_sizes, int n_in,
                              void* d_out, int out_size)
{
    const float* x     = (const float*)d_in[0];
    const float* w_qkv = (const float*)d_in[1];
    const float* w_out = (const float*)d_in[2];
    float*       out   = (float*)d_out;

    float *qkv_p, *w2_p;
    cudaGetSymbolAddress((void**)&qkv_p, g_qkv);
    cudaGetSymbolAddress((void**)&w2_p,  g_W2);

    dim3 gg(NPIX / 128, 2, BATCH);

    // 1) q and v projections (tf32 tensor cores, pipelined, conflict-free)
    gemm_tf32<<<gg, 256>>>(w_qkv, x, qkv_p, CDIM,
                           0, (size_t)CDIM * NPIX, (size_t)256 * NPIX, 256);
    // 2) softmax over n (in place on q rows)
    softmax_n_kernel<<<BATCH * HID, 256>>>();
    // 3+4) fused softmax over d + partial ctx (tf32 MMA), deterministic reduce
    ctx_part_kernel<<<BATCH * NHEADS * NCHUNK, 256>>>();
    ctx_reduce_kernel<<<65536 / 256, 256>>>();
    // 5) compose W2 = w_out o ctx
    w2_kernel<<<(BATCH * CDIM * HID) / 256, 256>>>(w_out);
    // 6) y = W2 @ q (tf32, pipelined, conflict-free)
    gemm_tf32<<<gg, 256>>>(w2_p, qkv_p, out, HID,
                           (size_t)CDIM * HID, (size_t)256 * NPIX, (size_t)CDIM * NPIX, 128);
}

// round 7
// speedup vs baseline: 4.1452x; 1.2314x over previous
#include <cuda_runtime.h>
#include <math.h>
#include <stdint.h>

#define BATCH  16
#define CDIM   256
#define NPIX   4096
#define NHEADS 4
#define DHEAD  32
#define HID    128
#define NCHUNK 32
#define CHW    128
#define PAD    20            // As pitch: frag bank = (20g+t)%32, all 32 distinct
#define BPITCH 136           // Bs pitch: 136%32==8 -> frag bank = 8t+g, all 32 distinct
#define CPITCH 132           // ctx smem pitch

// Scratch (device globals: allocation-free per harness rules)
__device__ float  g_qkv [BATCH * 256 * NPIX];                // rows 0-127 = raw q, 128-255 = v
__device__ float  g_ctxp[NCHUNK * BATCH * NHEADS * DHEAD * DHEAD];
__device__ float  g_W2  [BATCH * CDIM * HID];
__device__ float2 g_stats[BATCH * HID];                      // per q-row {max, 1/sumexp}

__device__ __forceinline__ uint32_t f2tf32(float f)
{
    uint32_t u;
    asm("cvt.rna.tf32.f32 %0, %1;" : "=r"(u) : "f"(f));
    return u;
}

__device__ __forceinline__ void mma_tf32(float c[4],
    uint32_t a0, uint32_t a1, uint32_t a2, uint32_t a3,
    uint32_t b0, uint32_t b1)
{
    asm volatile(
        "mma.sync.aligned.m16n8k8.row.col.f32.tf32.tf32.f32 "
        "{%0,%1,%2,%3}, {%4,%5,%6,%7}, {%8,%9}, {%0,%1,%2,%3};"
        : "+f"(c[0]), "+f"(c[1]), "+f"(c[2]), "+f"(c[3])
        : "r"(a0), "r"(a1), "r"(a2), "r"(a3), "r"(b0), "r"(b1));
}

__device__ __forceinline__ uint4 cvt4(float4 v)
{
    uint4 u;
    u.x = f2tf32(v.x); u.y = f2tf32(v.y); u.z = f2tf32(v.z); u.w = f2tf32(v.w);
    return u;
}

__device__ __forceinline__ float4 normexp4(float4 v, float2 st)
{
    float4 r;
    r.x = __expf(v.x - st.x) * st.y;
    r.y = __expf(v.y - st.x) * st.y;
    r.z = __expf(v.z - st.x) * st.y;
    r.w = __expf(v.w - st.x) * st.y;
    return r;
}

// ---------------------------------------------------------------------------
// tf32 tensor-core GEMM, double-buffered, conflict-free smem.
// If stats != nullptr, the B operand rows are transformed exp(x-m)*inv on the
// fly (softmax-n applied during load): row r of B uses stats[b*128 + r].
// ---------------------------------------------------------------------------
__global__ void __launch_bounds__(256)
gemm_tf32(const float* __restrict__ A, const float* __restrict__ B,
          float* __restrict__ C, int K,
          size_t sA, size_t sB, size_t sC, int aJump,
          const float2* __restrict__ stats)
{
    __shared__ uint32_t As[2][128][PAD];      // [buf][m][k]
    __shared__ uint32_t Bs[2][16][BPITCH];    // [buf][k][n]

    int b = blockIdx.z;
    const float* Ab = A + (size_t)b * sA + (size_t)(blockIdx.y * aJump) * K;
    const float* Bb = B + (size_t)b * sB + blockIdx.x * 128;
    float*       Cb = C + (size_t)b * sC + (size_t)(blockIdx.y * 128) * NPIX + blockIdx.x * 128;
    const float2* stb = stats ? stats + b * HID : nullptr;

    int tid  = threadIdx.x;
    int lane = tid & 31, warp = tid >> 5;
    int g = lane >> 2, t = lane & 3;
    int wm = (warp >> 1) * 32;
    int wn = (warp & 1) * 64;

    int arow = tid >> 1, akb = (tid & 1) * 8;     // A loader: 128 rows x 16 k
    int bk   = tid >> 4, bnb = (tid & 15) * 8;    // B loader: 16 k x 128 n

    const float* aPtr = &Ab[(size_t)arow * K + akb];
    const float* bPtr = &Bb[(size_t)bk * NPIX + bnb];

    float acc[2][8][4] = {};
    float4 ra0, ra1, rb0, rb1;

    // prologue: load + stage tile 0
    ra0 = *(const float4*)&aPtr[0];
    ra1 = *(const float4*)&aPtr[4];
    rb0 = *(const float4*)&bPtr[0];
    rb1 = *(const float4*)&bPtr[4];
    if (stb) {
        float2 st = stb[bk];
        rb0 = normexp4(rb0, st);
        rb1 = normexp4(rb1, st);
    }
    *(uint4*)&As[0][arow][akb]     = cvt4(ra0);
    *(uint4*)&As[0][arow][akb + 4] = cvt4(ra1);
    *(uint4*)&Bs[0][bk][bnb]       = cvt4(rb0);
    *(uint4*)&Bs[0][bk][bnb + 4]   = cvt4(rb1);
    __syncthreads();

    int nsteps = K >> 4;
    for (int s = 0; s < nsteps; s++) {
        int cur = s & 1;
        int has_next = (s + 1 < nsteps);

        if (has_next) {
            const float* ap = aPtr + (s + 1) * 16;
            const float* bp = bPtr + (size_t)(s + 1) * 16 * NPIX;
            ra0 = *(const float4*)&ap[0];
            ra1 = *(const float4*)&ap[4];
            rb0 = *(const float4*)&bp[0];
            rb1 = *(const float4*)&bp[4];
            if (stb) {
                float2 st = stb[(s + 1) * 16 + bk];
                rb0 = normexp4(rb0, st);
                rb1 = normexp4(rb1, st);
            }
        }

#pragma unroll
        for (int k8 = 0; k8 < 16; k8 += 8) {
            uint32_t af[2][4], bf[8][2];
#pragma unroll
            for (int mt = 0; mt < 2; mt++) {
                int r = wm + mt * 16 + g;
                af[mt][0] = As[cur][r    ][k8 + t];
                af[mt][1] = As[cur][r + 8][k8 + t];
                af[mt][2] = As[cur][r    ][k8 + t + 4];
                af[mt][3] = As[cur][r + 8][k8 + t + 4];
            }
#pragma unroll
            for (int nt = 0; nt < 8; nt++) {
                int c = wn + nt * 8 + g;
                bf[nt][0] = Bs[cur][k8 + t    ][c];
                bf[nt][1] = Bs[cur][k8 + t + 4][c];
            }
#pragma unroll
            for (int mt = 0; mt < 2; mt++)
#pragma unroll
                for (int nt = 0; nt < 8; nt++)
                    mma_tf32(acc[mt][nt],
                             af[mt][0], af[mt][1], af[mt][2], af[mt][3],
                             bf[nt][0], bf[nt][1]);
        }

        if (has_next) {
            int nxt = cur ^ 1;
            *(uint4*)&As[nxt][arow][akb]     = cvt4(ra0);
            *(uint4*)&As[nxt][arow][akb + 4] = cvt4(ra1);
            *(uint4*)&Bs[nxt][bk][bnb]       = cvt4(rb0);
            *(uint4*)&Bs[nxt][bk][bnb + 4]   = cvt4(rb1);
            __syncthreads();
        }
    }

#pragma unroll
    for (int mt = 0; mt < 2; mt++) {
        int r0 = wm + mt * 16 + g;
#pragma unroll
        for (int nt = 0; nt < 8; nt++) {
            int c0 = wn + nt * 8 + 2 * t;
            float2 lo = {acc[mt][nt][0], acc[mt][nt][1]};
            float2 hi = {acc[mt][nt][2], acc[mt][nt][3]};
            *(float2*)&Cb[(size_t)r0       * NPIX + c0] = lo;
            *(float2*)&Cb[(size_t)(r0 + 8) * NPIX + c0] = hi;
        }
    }
}

// ---------------------------------------------------------------------------
// Row stats for softmax over n: per q-row {max, 1/sum(exp(x-max))}.
// Same reduction order as the old softmax_n kernel (bit-identical m, s).
// ---------------------------------------------------------------------------
__global__ void stats_kernel()
{
    int r = blockIdx.x;                 // 0..2047
    int b = r >> 7, q = r & 127;
    const float* row = g_qkv + (size_t)b * 256 * NPIX + (size_t)q * NPIX;
    int tid = threadIdx.x;

    float v[16];
    float m = -1e30f;
#pragma unroll
    for (int i = 0; i < 16; i++) { v[i] = row[tid + i * 256]; m = fmaxf(m, v[i]); }

    __shared__ float red[8];
#pragma unroll
    for (int o = 16; o > 0; o >>= 1) m = fmaxf(m, __shfl_xor_sync(~0u, m, o));
    if ((tid & 31) == 0) red[tid >> 5] = m;
    __syncthreads();
    m = red[0];
#pragma unroll
    for (int i = 1; i < 8; i++) m = fmaxf(m, red[i]);
    __syncthreads();

    float s = 0.f;
#pragma unroll
    for (int i = 0; i < 16; i++) s += __expf(v[i] - m);
#pragma unroll
    for (int o = 16; o > 0; o >>= 1) s += __shfl_xor_sync(~0u, s, o);
    if ((tid & 31) == 0) red[tid >> 5] = s;
    __syncthreads();
    if (tid == 0) {
        s = red[0];
#pragma unroll
        for (int i = 1; i < 8; i++) s += red[i];
        g_stats[r] = make_float2(m, 1.0f / s);
    }
}

// ---------------------------------------------------------------------------
// Fused: softmax-n applied on load + per-column softmax over d + partial
// context via tf32 MMA. One block per (b, h, n-chunk of 128).
// ---------------------------------------------------------------------------
__global__ void __launch_bounds__(256) ctx_part_kernel()
{
    int bid = blockIdx.x;
    int ch  = bid & 31;
    int bh  = bid >> 5;
    int b   = bh >> 2, h = bh & 3;
    int n0  = ch * CHW;

    const float* qp = g_qkv + ((size_t)b * 256 + h * DHEAD) * NPIX + n0;
    const float* vp = g_qkv + ((size_t)b * 256 + 128 + h * DHEAD) * NPIX + n0;

    __shared__ float kst[DHEAD][CPITCH];
    __shared__ float vst[DHEAD][CPITCH];

    int tid = threadIdx.x;

#pragma unroll
    for (int r = 0; r < 4; r++) {
        int idx = tid + r * 256;
        int row = idx >> 5;             // d 0..31
        int col = (idx & 31) * 4;
        float2 st = g_stats[(b << 7) + (h << 5) + row];
        float4 qv = *(const float4*)&qp[(size_t)row * NPIX + col];
        *(float4*)&kst[row][col] = normexp4(qv, st);   // softmax-n applied
        *(float4*)&vst[row][col] = *(const float4*)&vp[(size_t)row * NPIX + col];
    }
    __syncthreads();

    // per-column softmax over d (on the softmax-n'd values)
    if (tid < CHW) {
        float e[DHEAD];
        float m = -1e30f;
#pragma unroll
        for (int d = 0; d < DHEAD; d++) { e[d] = kst[d][tid]; m = fmaxf(m, e[d]); }
        float s = 0.f;
#pragma unroll
        for (int d = 0; d < DHEAD; d++) { e[d] = __expf(e[d] - m); s += e[d]; }
        float inv = 1.0f / s;
#pragma unroll
        for (int d = 0; d < DHEAD; d++) kst[d][tid] = e[d] * inv;
    }
    __syncthreads();

    int lane = tid & 31, warp = tid >> 5;
    int g = lane >> 2, t = lane & 3;
    int mrow = (warp >> 2) * 16;
    int ncol = (warp & 3) * 8;

    float acc[4] = {};
#pragma unroll
    for (int k8 = 0; k8 < CHW; k8 += 8) {
        uint32_t a0 = f2tf32(kst[mrow + g    ][k8 + t]);
        uint32_t a1 = f2tf32(kst[mrow + g + 8][k8 + t]);
        uint32_t a2 = f2tf32(kst[mrow + g    ][k8 + t + 4]);
        uint32_t a3 = f2tf32(kst[mrow + g + 8][k8 + t + 4]);
        uint32_t b0 = f2tf32(vst[ncol + g][k8 + t]);
        uint32_t b1 = f2tf32(vst[ncol + g][k8 + t + 4]);
        mma_tf32(acc, a0, a1, a2, a3, b0, b1);
    }

    float* pp = g_ctxp + (size_t)ch * (64 * 1024) + (size_t)bh * 1024;
    float2 lo = {acc[0], acc[1]};
    float2 hi = {acc[2], acc[3]};
    *(float2*)&pp[(mrow + g    ) * DHEAD + ncol + 2 * t] = lo;
    *(float2*)&pp[(mrow + g + 8) * DHEAD + ncol + 2 * t] = hi;
}

// ---------------------------------------------------------------------------
// Merged: reduce ctx partials (fixed order) + compose W2 = w_out o ctx.
// One block per (b,h); 256 threads.
// ---------------------------------------------------------------------------
__global__ void __launch_bounds__(256) ctxw2_kernel(const float* __restrict__ w_out)
{
    int bh = blockIdx.x;                // b*4 + h
    int b  = bh >> 2, h = bh & 3;

    __shared__ float ctx[1024];         // [k][v] 32x32
    int tid = threadIdx.x;

#pragma unroll
    for (int j = 0; j < 4; j++) {
        int e = tid + j * 256;
        float s = 0.f;
#pragma unroll
        for (int ch = 0; ch < NCHUNK; ch++)
            s += g_ctxp[(size_t)ch * 65536 + (size_t)bh * 1024 + e];
        ctx[e] = s;
    }
    __syncthreads();

    // W2[b][o][h*32+kk] = sum_v w_out[o][h*32+v] * ctx[kk][v]
    int o = tid;
    float wrow[32];
#pragma unroll
    for (int v = 0; v < 32; v++) wrow[v] = w_out[o * HID + h * DHEAD + v];

    float* w2p = g_W2 + ((size_t)b * CDIM + o) * HID + h * DHEAD;
#pragma unroll
    for (int kk = 0; kk < 32; kk++) {
        float s = 0.f;
#pragma unroll
        for (int v = 0; v < 32; v++) s = fmaf(wrow[v], ctx[kk * 32 + v], s);
        w2p[kk] = s;
    }
}

// ---------------------------------------------------------------------------
extern "C" void kernel_launch(void* const* d_in, const int* in_sizes, int n_in,
                              void* d_out, int out_size)
{
    const float* x     = (const float*)d_in[0];
    const float* w_qkv = (const float*)d_in[1];
    const float* w_out = (const float*)d_in[2];
    float*       out   = (float*)d_out;

    float  *qkv_p, *w2_p;
    float2 *st_p;
    cudaGetSymbolAddress((void**)&qkv_p, g_qkv);
    cudaGetSymbolAddress((void**)&w2_p,  g_W2);
    cudaGetSymbolAddress((void**)&st_p,  g_stats);

    dim3 gg(NPIX / 128, 2, BATCH);

    // 1) q and v projections (raw q stored; no softmax pass needed)
    gemm_tf32<<<gg, 256>>>(w_qkv, x, qkv_p, CDIM,
                           0, (size_t)CDIM * NPIX, (size_t)256 * NPIX, 256, nullptr);
    // 2) per-row softmax-n stats only
    stats_kernel<<<BATCH * HID, 256>>>();
    // 3) fused softmax-n(load) + softmax-d + partial ctx (tf32 MMA)
    ctx_part_kernel<<<BATCH * NHEADS * NCHUNK, 256>>>();
    // 4) merged reduce + W2 compose
    ctxw2_kernel<<<BATCH * NHEADS, 256>>>(w_out);
    // 5) y = W2 @ softmax_n(q), normalization applied in B-loader
    gemm_tf32<<<gg, 256>>>(w2_p, qkv_p, out, HID,
                           (size_t)CDIM * HID, (size_t)256 * NPIX, (size_t)CDIM * NPIX, 128,
                           st_p);
}